// round 7
// baseline (speedup 1.0000x reference)
#include <cuda_runtime.h>
#include <cuda_bf16.h>
#include <cstdint>

// Problem constants
#define NSEQ   2048
#define HD     64
#define NROT   32
#define NROWS  131072
#define ROWS_PER_CTA 64
#define NCTAS  (NROWS / ROWS_PER_CTA)  // 2048

#define STRIDE_AB 72   // bf16 per padded B row (144B): conflict-free LDSM rows
#define STRIDE_ST 68   // floats per padded staging row (272B, 16B aligned)

// Device scratch: pre-split B = M^T in bf16 hi/lo, padded rows
__device__ __align__(16) __nv_bfloat16 g_B[2][HD * STRIDE_AB];

// ---------------------------------------------------------------------------
// Setup: M = T0*...*T31 * R (column t per thread, no cross-thread deps).
// Emits B[n][k] = M[k][n] in bf16 hi/lo, then signals dependent launch (PDL).
// ---------------------------------------------------------------------------
__global__ void build_M_kernel(const float* __restrict__ thetas,
                               const float* __restrict__ tscale,
                               const float* __restrict__ R,
                               const int*   __restrict__ pairs) {
    __shared__ float Ms[HD * HD];
    __shared__ float CT[NROT], ST[NROT];
    __shared__ int   PR[2 * NROT];
    const int t = threadIdx.x;  // 0..63

    if (t < 2 * NROT) PR[t] = pairs[t];
    if (t < NROT) {
        float sv, cv;
        sincosf(thetas[t] * tscale[0], &sv, &cv);
        CT[t] = cv;
        ST[t] = sv;
    }
#pragma unroll 4
    for (int d = 0; d < HD; d++) Ms[d * HD + t] = R[d * HD + t];
    __syncthreads();

    for (int k = NROT - 1; k >= 0; k--) {
        const int i = PR[2 * k];
        const int j = PR[2 * k + 1];
        const float cv = CT[k], sv = ST[k];
        const float a = Ms[i * HD + t];
        const float b = Ms[j * HD + t];
        if (i == j) {
            Ms[i * HD + t] = sv * a;
        } else {
            Ms[i * HD + t] = cv * a - sv * b;
            Ms[j * HD + t] = sv * a + cv * b;
        }
    }
#pragma unroll 4
    for (int k = 0; k < HD; k++) {
        const float v = Ms[k * HD + t];
        const __nv_bfloat16 hi = __float2bfloat16(v);
        const __nv_bfloat16 lo = __float2bfloat16(v - __bfloat162float(hi));
        g_B[0][t * STRIDE_AB + k] = hi;
        g_B[1][t * STRIDE_AB + k] = lo;
    }
    __threadfence();
    asm volatile("griddepcontrol.launch_dependents;");
}

// ---------------------------------------------------------------------------
// PTX helpers
// ---------------------------------------------------------------------------
__device__ __forceinline__ uint32_t smem_u32(const void* p) {
    uint32_t a;
    asm("{ .reg .u64 t; cvta.to.shared.u64 t, %1; cvt.u32.u64 %0, t; }"
        : "=r"(a) : "l"(p));
    return a;
}
__device__ __forceinline__ void ldsm_x4(uint32_t addr, uint32_t& r0, uint32_t& r1,
                                        uint32_t& r2, uint32_t& r3) {
    asm volatile("ldmatrix.sync.aligned.m8n8.x4.shared.b16 {%0,%1,%2,%3}, [%4];"
                 : "=r"(r0), "=r"(r1), "=r"(r2), "=r"(r3) : "r"(addr));
}
__device__ __forceinline__ void mma16816(float* d,
                                         uint32_t a0, uint32_t a1, uint32_t a2, uint32_t a3,
                                         uint32_t b0, uint32_t b1) {
    asm volatile(
        "mma.sync.aligned.m16n8k16.row.col.f32.bf16.bf16.f32 "
        "{%0,%1,%2,%3}, {%4,%5,%6,%7}, {%8,%9}, {%0,%1,%2,%3};"
        : "+f"(d[0]), "+f"(d[1]), "+f"(d[2]), "+f"(d[3])
        : "r"(a0), "r"(a1), "r"(a2), "r"(a3), "r"(b0), "r"(b1));
}
// Split float2 (k-even, k-odd) into packed bf16x2 hi and lo-residual
__device__ __forceinline__ void split_pair(float2 v, uint32_t& hi, uint32_t& lo) {
    uint32_t h;
    asm("cvt.rn.bf16x2.f32 %0, %1, %2;" : "=r"(h) : "f"(v.y), "f"(v.x));
    const float h0 = __uint_as_float(h << 16);
    const float h1 = __uint_as_float(h & 0xffff0000u);
    uint32_t l;
    asm("cvt.rn.bf16x2.f32 %0, %1, %2;" : "=r"(l) : "f"(v.y - h1), "f"(v.x - h0));
    hi = h;
    lo = l;
}
__device__ __forceinline__ void cp_async16(uint32_t smem_addr, const void* gptr) {
    asm volatile("cp.async.cg.shared.global [%0], [%1], 16;"
                 :: "r"(smem_addr), "l"(gptr));
}

// ---------------------------------------------------------------------------
// Main kernel: 64 rows/CTA, 4 warps x 16 rows.
//  - A fragments loaded DIRECTLY from global (LDG.64, fragment layout) and
//    hi/lo-split in registers: x never touches shared memory.
//  - B staged via cp.async, fragments via ldmatrix.x4 (conflict-free).
//  - PDL: prologue overlaps build_M; griddepcontrol.wait guards g_B.
//  - Register RoPE, staged coalesced float4 store. Two barriers total.
// ---------------------------------------------------------------------------
__global__ void __launch_bounds__(128, 6)
rotary_mma_kernel(const float* __restrict__ x,
                  const float* __restrict__ inv_freq,
                  float* __restrict__ out) {
    static __shared__ __align__(16) __nv_bfloat16 Bsm[2][HD * STRIDE_AB];  // 18432B
    static __shared__ __align__(16) float STGm[ROWS_PER_CTA * STRIDE_ST];  // 17408B
    __shared__ float2 TR[4][NROT];                                          // 1024B

    const int t    = threadIdx.x;
    const int wid  = t >> 5;
    const int lane = t & 31;
    const int bid  = blockIdx.x;
    const int r    = lane >> 2;   // row-in-quad
    const int c    = lane & 3;    // col-quad

    // ---- 1. x fragment loads straight from global (16 LDG.64, MLP=16) ----
    float2 xp[16];
    {
        const float* xw = x + (bid * ROWS_PER_CTA + wid * 16) * HD;
#pragma unroll
        for (int ks = 0; ks < 4; ks++) {
            const int kb = 16 * ks + 2 * c;
            xp[ks * 4 + 0] = *(const float2*)(xw + r * HD + kb);
            xp[ks * 4 + 1] = *(const float2*)(xw + (r + 8) * HD + kb);
            xp[ks * 4 + 2] = *(const float2*)(xw + r * HD + kb + 8);
            xp[ks * 4 + 3] = *(const float2*)(xw + (r + 8) * HD + kb + 8);
        }
    }

    // ---- 2. Trig (warp-private): position = bid*4 + wid ----
    {
        const int pos = (bid * 4 + wid) & (NSEQ - 1);
        float sv, cv;
        sincosf((float)pos * inv_freq[lane], &sv, &cv);
        TR[wid][lane] = make_float2(cv, sv);
    }

    // ---- 3. Wait for build_M (PDL), then stage B via cp.async ----
    asm volatile("griddepcontrol.wait;" ::: "memory");
    {
        const uint32_t bdst = smem_u32(Bsm);
        const char* bsrc = (const char*)g_B;
#pragma unroll
        for (int i = 0; i < 9; i++) {
            const int idx = i * 128 + t;   // 1152 16B chunks
            cp_async16(bdst + idx * 16, bsrc + idx * 16);
        }
        asm volatile("cp.async.commit_group;");
    }

    // ---- 4. Convert x to bf16 hi/lo fragments in registers ----
    uint32_t ahi[16], alo[16];
#pragma unroll
    for (int i = 0; i < 16; i++) split_pair(xp[i], ahi[i], alo[i]);

    asm volatile("cp.async.wait_group 0;");
    __syncthreads();   // B visible to all warps

    // ---- 5. GEMM: warp owns rows [wid*16, wid*16+16), all 64 cols ----
    float acc[8][4];
#pragma unroll
    for (int n = 0; n < 8; n++)
#pragma unroll
        for (int u = 0; u < 4; u++) acc[n][u] = 0.0f;

    const int m  = lane >> 3;
    const int rr = lane & 7;
    const uint32_t b_off = (uint32_t)(rr * STRIDE_AB) * 2 + (uint32_t)((m & 1) << 4)
                         + (uint32_t)((m >> 1) * 8 * STRIDE_AB * 2);
    const uint32_t bhi_base = smem_u32(Bsm[0]) + b_off;
    const uint32_t blo_base = smem_u32(Bsm[1]) + b_off;

#pragma unroll
    for (int ks = 0; ks < 4; ks++) {
        const uint32_t ah0 = ahi[ks * 4 + 0], ah1 = ahi[ks * 4 + 1];
        const uint32_t ah2 = ahi[ks * 4 + 2], ah3 = ahi[ks * 4 + 3];
        const uint32_t al0 = alo[ks * 4 + 0], al1 = alo[ks * 4 + 1];
        const uint32_t al2 = alo[ks * 4 + 2], al3 = alo[ks * 4 + 3];
#pragma unroll
        for (int np = 0; np < 4; np++) {   // n-tile pair (2np, 2np+1)
            const uint32_t boff = (uint32_t)(np * 16 * STRIDE_AB * 2) + ks * 32;
            uint32_t bh0, bh1, bh2, bh3, bl0, bl1, bl2, bl3;
            ldsm_x4(bhi_base + boff, bh0, bh1, bh2, bh3);
            ldsm_x4(blo_base + boff, bl0, bl1, bl2, bl3);
            mma16816(acc[2 * np],     ah0, ah1, ah2, ah3, bh0, bh1);
            mma16816(acc[2 * np],     ah0, ah1, ah2, ah3, bl0, bl1);
            mma16816(acc[2 * np],     al0, al1, al2, al3, bh0, bh1);
            mma16816(acc[2 * np + 1], ah0, ah1, ah2, ah3, bh2, bh3);
            mma16816(acc[2 * np + 1], ah0, ah1, ah2, ah3, bl2, bl3);
            mma16816(acc[2 * np + 1], al0, al1, al2, al3, bh2, bh3);
        }
    }

    // ---- 6. RoPE in registers -> padded staging (conflict-free STS.32) ----
    // D frag: {c0,c1} = row (wid*16+r), cols (2p,2p+1); {c2,c3} = row+8. p = nt*4+c.
    {
        const int row0 = wid * 16 + r;
#pragma unroll
        for (int nt = 0; nt < 8; nt++) {
            const int p  = nt * 4 + c;
            const float2 cs = TR[wid][p];
            STGm[row0 * STRIDE_ST + p]            = (acc[nt][0] * cs.x - acc[nt][1] * cs.y) * 32.0f;
            STGm[row0 * STRIDE_ST + p + 32]       = (acc[nt][0] * cs.y + acc[nt][1] * cs.x) * 32.0f;
            STGm[(row0 + 8) * STRIDE_ST + p]      = (acc[nt][2] * cs.x - acc[nt][3] * cs.y) * 32.0f;
            STGm[(row0 + 8) * STRIDE_ST + p + 32] = (acc[nt][2] * cs.y + acc[nt][3] * cs.x) * 32.0f;
        }
    }
    __syncthreads();

    // ---- 7. Coalesced float4 store ----
    {
        float4* og = (float4*)out + (long long)bid * 1024;
#pragma unroll
        for (int it = 0; it < 8; it++) {
            const int f   = it * 128 + t;
            const int row = f >> 4;
            const int c4  = f & 15;
            og[f] = *(const float4*)(STGm + row * STRIDE_ST + c4 * 4);
        }
    }
}

// ---------------------------------------------------------------------------
// kernel_launch: 0:x 1:thetas 2:theta_scale 3:r_matrix 4:inv_freq 5:pairs
// ---------------------------------------------------------------------------
extern "C" void kernel_launch(void* const* d_in, const int* in_sizes, int n_in,
                              void* d_out, int out_size) {
    const float* x        = (const float*)d_in[0];
    const float* thetas   = (const float*)d_in[1];
    const float* tscale   = (const float*)d_in[2];
    const float* R        = (const float*)d_in[3];
    const float* inv_freq = (const float*)d_in[4];
    const int*   pairs    = (const int*)d_in[5];
    float* out = (float*)d_out;

    build_M_kernel<<<1, 64>>>(thetas, tscale, R, pairs);

    // Main kernel with programmatic dependent launch: prologue overlaps build_M
    cudaLaunchConfig_t cfg = {};
    cfg.gridDim  = dim3(NCTAS, 1, 1);
    cfg.blockDim = dim3(128, 1, 1);
    cfg.dynamicSmemBytes = 0;
    cfg.stream = 0;
    cudaLaunchAttribute attr[1];
    attr[0].id = cudaLaunchAttributeProgrammaticStreamSerialization;
    attr[0].val.programmaticStreamSerializationAllowed = 1;
    cfg.attrs = attr;
    cfg.numAttrs = 1;
    cudaLaunchKernelEx(&cfg, rotary_mma_kernel, x, inv_freq, out);
}